// round 3
// baseline (speedup 1.0000x reference)
#include <cuda_runtime.h>
#include <cuda_bf16.h>
#include <math.h>

// Problem dims
#define D        1024
#define S        32768
#define VOCAB    50257
#define CDIM     2048

// K2 config: 512 blocks * 4 warps = 2048 warps, 16 rows each, ONE wave at 4 CTA/SM
#define ATT_BLOCKS 512
#define ATT_WARPS  4
#define ROWS_PER_WARP (S / (ATT_BLOCKS * ATT_WARPS))   // 16

#define K4_BLOCKS ((VOCAB + 15) / 16)                  // 3142

// Scratch (device globals; no allocation allowed)
// partial layout per block: [0]=m, [1]=z, [4..1027]=acc (16B aligned: stride 1028 floats)
__device__ float g_part[ATT_BLOCKS * 1028];
__device__ float g_concat[CDIM];          // [0..1023]=x (relu hidden), [1024..2047]=attn
__device__ float g_logits[VOCAB];
__device__ float g_k4m[K4_BLOCKS];        // per-block logit max
__device__ float g_k4z[K4_BLOCKS];        // per-block sum exp(l - m_b)
__device__ float g_stats[2];              // M, 1/Z for final softmax

__device__ __forceinline__ float warp_reduce_sum(float v) {
#pragma unroll
    for (int o = 16; o > 0; o >>= 1) v += __shfl_xor_sync(0xffffffffu, v, o);
    return v;
}
__device__ __forceinline__ float warp_reduce_max(float v) {
#pragma unroll
    for (int o = 16; o > 0; o >>= 1) v = fmaxf(v, __shfl_xor_sync(0xffffffffu, v, o));
    return v;
}

// ---------------------------------------------------------------------------
// K1: x = relu(W_h @ input + b_h); one warp per output row. Writes g_concat[0..D)
// ---------------------------------------------------------------------------
__global__ void k1_hidden(const float* __restrict__ inp,
                          const float* __restrict__ Wh,
                          const float* __restrict__ bh) {
    int warp = threadIdx.x >> 5, lane = threadIdx.x & 31;
    int row  = blockIdx.x * 8 + warp;      // 128 blocks * 8 warps = 1024 rows
    const float4* w4  = (const float4*)(Wh + (size_t)row * D);
    const float4* in4 = (const float4*)inp;
    float acc = 0.f;
#pragma unroll
    for (int k = 0; k < 8; k++) {
        float4 a = w4[k * 32 + lane];
        float4 b = in4[k * 32 + lane];
        acc += a.x * b.x + a.y * b.y + a.z * b.z + a.w * b.w;
    }
    acc = warp_reduce_sum(acc);
    if (lane == 0) g_concat[row] = fmaxf(acc + bh[row], 0.f);
}

// ---------------------------------------------------------------------------
// K2: fused flash-style attention (single 134 MB pass), software-pipelined:
// row r+1's loads are issued BEFORE row r's shfl-reduce, hiding the ~130cyc
// reduction chain under DRAM latency (cross-row MLP ~= 2).
// 512 blocks x 128 threads = one full wave at 4 CTAs/SM.
// ---------------------------------------------------------------------------
__global__ void __launch_bounds__(128, 4) k2_attn(const float* __restrict__ enc) {
    __shared__ float4 sq[D / 4];              // q (= x) as float4        : 4 KB
    __shared__ float  swacc[ATT_WARPS * D];   // per-warp scaled accums   : 16 KB
    __shared__ float  sm_[ATT_WARPS];
    __shared__ float  sz_[ATT_WARPS];

    int tid = threadIdx.x, warp = tid >> 5, lane = tid & 31;

    for (int i = tid; i < D / 4; i += blockDim.x)
        sq[i] = ((const float4*)g_concat)[i];
    __syncthreads();

    int gw   = blockIdx.x * ATT_WARPS + warp;
    int row0 = gw * ROWS_PER_WARP;

    float  m = -INFINITY, z = 0.f;
    float4 acc[8];
#pragma unroll
    for (int k = 0; k < 8; k++) acc[k] = make_float4(0.f, 0.f, 0.f, 0.f);

    // prologue: load row 0
    float4 rv[8];
    {
        const float4* e4 = (const float4*)(enc + (size_t)row0 * D);
#pragma unroll
        for (int k = 0; k < 8; k++) rv[k] = e4[k * 32 + lane];
    }

    for (int r = 0; r < ROWS_PER_WARP; r++) {
        // dot with q (rv already resident)
        float p = 0.f;
#pragma unroll
        for (int k = 0; k < 8; k++) {
            float4 qv = sq[k * 32 + lane];
            p += rv[k].x * qv.x + rv[k].y * qv.y + rv[k].z * qv.z + rv[k].w * qv.w;
        }

        // prefetch next row BEFORE the reduce (guarded by clamped index; the
        // redundant last prefetch re-reads an L2-hot row, harmless)
        int rn = (r + 1 < ROWS_PER_WARP) ? (r + 1) : r;
        const float4* e4n = (const float4*)(enc + (size_t)(row0 + rn) * D);
        float4 nv[8];
#pragma unroll
        for (int k = 0; k < 8; k++) nv[k] = e4n[k * 32 + lane];

        p = warp_reduce_sum(p);               // latency hidden under nv loads

        float nm = fmaxf(m, p);
        float sc = __expf(m - nm);
        float w  = __expf(p - nm);
#pragma unroll
        for (int k = 0; k < 8; k++) {
            acc[k].x = acc[k].x * sc + w * rv[k].x;
            acc[k].y = acc[k].y * sc + w * rv[k].y;
            acc[k].z = acc[k].z * sc + w * rv[k].z;
            acc[k].w = acc[k].w * sc + w * rv[k].w;
        }
        z = z * sc + w;
        m = nm;
#pragma unroll
        for (int k = 0; k < 8; k++) rv[k] = nv[k];
    }

    if (lane == 0) sm_[warp] = m;
    __syncthreads();

    float mb = sm_[0];
#pragma unroll
    for (int wv = 1; wv < ATT_WARPS; wv++) mb = fmaxf(mb, sm_[wv]);

    float f = __expf(m - mb);
    if (lane == 0) sz_[warp] = z * f;
#pragma unroll
    for (int k = 0; k < 8; k++) {
        float4 s = make_float4(acc[k].x * f, acc[k].y * f, acc[k].z * f, acc[k].w * f);
        ((float4*)swacc)[warp * (D / 4) + k * 32 + lane] = s;
    }
    __syncthreads();

    // Reduce 4 warp partials; 128 threads cover 256 float4 columns (2 each)
    float* outp = &g_part[blockIdx.x * 1028];
    for (int i = tid; i < D / 4; i += 128) {
        float4 s = make_float4(0.f, 0.f, 0.f, 0.f);
#pragma unroll
        for (int wv = 0; wv < ATT_WARPS; wv++) {
            float4 v = ((float4*)swacc)[wv * (D / 4) + i];
            s.x += v.x; s.y += v.y; s.z += v.z; s.w += v.w;
        }
        ((float4*)(outp + 4))[i] = s;         // offset 4 floats = 16B aligned
    }
    if (tid == 0) {
        float zz = 0.f;
#pragma unroll
        for (int wv = 0; wv < ATT_WARPS; wv++) zz += sz_[wv];
        outp[0] = mb;
        outp[1] = zz;
    }
}

// ---------------------------------------------------------------------------
// K3: combine ATT_BLOCKS partials -> attn vector; writes g_concat[D..2D)
// 32 blocks x 128 threads; 32 columns/block, 4 b-slices per column.
// ---------------------------------------------------------------------------
__global__ void k3_combine() {
    __shared__ float sf[ATT_BLOCKS];
    __shared__ float red[128];
    __shared__ float slice[128];
    int tid = threadIdx.x;

    float lm = -INFINITY;
    for (int b = tid; b < ATT_BLOCKS; b += 128) lm = fmaxf(lm, g_part[b * 1028]);
    red[tid] = lm; __syncthreads();
    for (int s = 64; s > 0; s >>= 1) {
        if (tid < s) red[tid] = fmaxf(red[tid], red[tid + s]);
        __syncthreads();
    }
    float M = red[0]; __syncthreads();

    float lz = 0.f;
    for (int b = tid; b < ATT_BLOCKS; b += 128) {
        float fb = __expf(g_part[b * 1028] - M);
        sf[b] = fb;
        lz += fb * g_part[b * 1028 + 1];
    }
    red[tid] = lz; __syncthreads();
    for (int s = 64; s > 0; s >>= 1) {
        if (tid < s) red[tid] += red[tid + s];
        __syncthreads();
    }
    float invZ = 1.0f / red[0];
    __syncthreads();

    // column sums: 32 columns per block, 4 slices of the b-range per column
    int col = blockIdx.x * 32 + (tid & 31);
    int sl  = tid >> 5;                       // 0..3
    float v = 0.f;
#pragma unroll 4
    for (int b = sl; b < ATT_BLOCKS; b += 4)
        v += sf[b] * g_part[b * 1028 + 4 + col];
    slice[tid] = v;
    __syncthreads();
    if (sl == 0) {
        float t = slice[tid] + slice[tid + 32] + slice[tid + 64] + slice[tid + 96];
        g_concat[D + col] = t * invZ;
    }
}

// ---------------------------------------------------------------------------
// K4: logits = W_out @ concat + b_out; one warp per vocab row (412 MB pass).
// Also emits per-block softmax partials (m_b, z_b) so K5 never re-reads logits.
// ---------------------------------------------------------------------------
__global__ void k4_logits(const float* __restrict__ Wo,
                          const float* __restrict__ bo) {
    __shared__ float4 sc[CDIM / 4];           // 8 KB
    __shared__ float  sl[16];
    int tid = threadIdx.x, warp = tid >> 5, lane = tid & 31;
    for (int i = tid; i < CDIM / 4; i += blockDim.x)
        sc[i] = ((const float4*)g_concat)[i];
    __syncthreads();

    int v = blockIdx.x * 16 + warp;
    int vc = (v < VOCAB) ? v : (VOCAB - 1);   // clamp; no early return (block reduce below)
    const float4* w4 = (const float4*)(Wo + (size_t)vc * CDIM);
    float p = 0.f;
#pragma unroll
    for (int k = 0; k < 16; k++) {
        float4 a = w4[k * 32 + lane];
        float4 q = sc[k * 32 + lane];
        p += a.x * q.x + a.y * q.y + a.z * q.z + a.w * q.w;
    }
    p = warp_reduce_sum(p);
    float logit = p + bo[vc];
    if (lane == 0) {
        if (v < VOCAB) g_logits[v] = logit;
        sl[warp] = (v < VOCAB) ? logit : -INFINITY;
    }
    __syncthreads();

    // warp 0: reduce the block's 16 logits to (m_b, z_b)
    if (warp == 0) {
        float l = (lane < 16) ? sl[lane] : -INFINITY;
        float mb = warp_reduce_max(l);
        float zb = warp_reduce_sum((lane < 16) ? __expf(l - mb) : 0.f);
        if (lane == 0) { g_k4m[blockIdx.x] = mb; g_k4z[blockIdx.x] = zb; }
    }
}

// ---------------------------------------------------------------------------
// K5: combine K4's per-block (m,z) partials -> global (M, 1/Z). 25KB read.
// ---------------------------------------------------------------------------
__global__ void k5_stats() {
    __shared__ float red[1024];
    int tid = threadIdx.x;
    float lm = -INFINITY;
    for (int i = tid; i < K4_BLOCKS; i += 1024) lm = fmaxf(lm, g_k4m[i]);
    red[tid] = lm; __syncthreads();
    for (int s = 512; s > 0; s >>= 1) {
        if (tid < s) red[tid] = fmaxf(red[tid], red[tid + s]);
        __syncthreads();
    }
    float M = red[0]; __syncthreads();
    float lz = 0.f;
    for (int i = tid; i < K4_BLOCKS; i += 1024)
        lz += g_k4z[i] * __expf(g_k4m[i] - M);
    red[tid] = lz; __syncthreads();
    for (int s = 512; s > 0; s >>= 1) {
        if (tid < s) red[tid] += red[tid + s];
        __syncthreads();
    }
    if (tid == 0) { g_stats[0] = M; g_stats[1] = 1.0f / red[0]; }
}

// ---------------------------------------------------------------------------
// K6: write softmax probabilities
// ---------------------------------------------------------------------------
__global__ void k6_out(float* __restrict__ out) {
    int i = blockIdx.x * 256 + threadIdx.x;
    if (i < VOCAB) out[i] = __expf(g_logits[i] - g_stats[0]) * g_stats[1];
}

// ---------------------------------------------------------------------------
extern "C" void kernel_launch(void* const* d_in, const int* in_sizes, int n_in,
                              void* d_out, int out_size) {
    const float* inp = (const float*)d_in[0];   // [1,1,1024]
    const float* enc = (const float*)d_in[1];   // [32768,1024]
    const float* Wh  = (const float*)d_in[2];   // [1024,1024]
    const float* bh  = (const float*)d_in[3];   // [1024]
    const float* Wo  = (const float*)d_in[4];   // [50257,2048]
    const float* bo  = (const float*)d_in[5];   // [50257]
    float* out = (float*)d_out;                 // [1,50257]

    k1_hidden<<<D / 8, 256>>>(inp, Wh, bh);
    k2_attn<<<ATT_BLOCKS, 128>>>(enc);
    k3_combine<<<D / 32, 128>>>();
    k4_logits<<<K4_BLOCKS, 512>>>(Wo, bo);
    k5_stats<<<1, 1024>>>();
    k6_out<<<(VOCAB + 255) / 256, 256>>>(out);
}

// round 4
// speedup vs baseline: 1.1190x; 1.1190x over previous
#include <cuda_runtime.h>
#include <cuda_bf16.h>
#include <math.h>

// Problem dims
#define D        1024
#define S        32768
#define VOCAB    50257
#define CDIM     2048

// K2: 296 blocks (2 per SM, one wave) * 8 warps; rows distributed grid-stride
#define ATT_BLOCKS 296
#define ATT_WARPS  8
#define NWARPS     (ATT_BLOCKS * ATT_WARPS)   // 2368

// Scratch (device globals; no allocation allowed)
// partial layout per block: [0]=m, [1]=z, [4..1027]=acc (16B aligned: stride 1028 floats)
__device__ float g_part[ATT_BLOCKS * 1028];
__device__ float g_concat[CDIM];          // [0..1023]=x (relu hidden), [1024..2047]=attn
__device__ float g_logits[VOCAB];
__device__ float g_stats[2];              // M, 1/Z for final softmax

__device__ __forceinline__ float warp_reduce_sum(float v) {
#pragma unroll
    for (int o = 16; o > 0; o >>= 1) v += __shfl_xor_sync(0xffffffffu, v, o);
    return v;
}

// ---------------------------------------------------------------------------
// K1: x = relu(W_h @ input + b_h); one warp per output row. Writes g_concat[0..D)
// ---------------------------------------------------------------------------
__global__ void k1_hidden(const float* __restrict__ inp,
                          const float* __restrict__ Wh,
                          const float* __restrict__ bh) {
    int warp = threadIdx.x >> 5, lane = threadIdx.x & 31;
    int row  = blockIdx.x * 8 + warp;      // 128 blocks * 8 warps = 1024 rows
    const float4* w4  = (const float4*)(Wh + (size_t)row * D);
    const float4* in4 = (const float4*)inp;
    float acc = 0.f;
#pragma unroll
    for (int k = 0; k < 8; k++) {
        float4 a = w4[k * 32 + lane];
        float4 b = in4[k * 32 + lane];
        acc += a.x * b.x + a.y * b.y + a.z * b.z + a.w * b.w;
    }
    acc = warp_reduce_sum(acc);
    if (lane == 0) g_concat[row] = fmaxf(acc + bh[row], 0.f);
}

// ---------------------------------------------------------------------------
// K2: fused flash-style attention, 2 rows per iteration with a SINGLE rescale:
//   nm = max(m, p0, p1); acc = acc*exp(m-nm) + w0*rv0 + w1*rv1
// 16 LDG.128 in flight per warp per iteration (2x MLP of the 1-row version),
// two interleaved shfl chains. 296 blocks x 8 warps = exactly 2 CTAs/SM, one wave.
// ---------------------------------------------------------------------------
__global__ void k2_attn(const float* __restrict__ enc) {
    __shared__ float4 sq[D / 4];              // q (= x) as float4        : 4 KB
    __shared__ float  swacc[ATT_WARPS * D];   // per-warp scaled accums   : 32 KB
    __shared__ float  sm_[ATT_WARPS];
    __shared__ float  sz_[ATT_WARPS];

    int tid = threadIdx.x, warp = tid >> 5, lane = tid & 31;

    for (int i = tid; i < D / 4; i += blockDim.x)
        sq[i] = ((const float4*)g_concat)[i];
    __syncthreads();

    int gw = blockIdx.x * ATT_WARPS + warp;

    float  m = -INFINITY, z = 0.f;
    float4 acc[8];
#pragma unroll
    for (int k = 0; k < 8; k++) acc[k] = make_float4(0.f, 0.f, 0.f, 0.f);

    for (int r = gw; r < S; r += 2 * NWARPS) {
        int  r1   = r + NWARPS;
        bool has1 = (r1 < S);
        const float4* e0 = (const float4*)(enc + (size_t)r * D);
        const float4* e1 = (const float4*)(enc + (size_t)(has1 ? r1 : r) * D);

        float4 rv0[8], rv1[8];
#pragma unroll
        for (int k = 0; k < 8; k++) rv0[k] = e0[k * 32 + lane];
#pragma unroll
        for (int k = 0; k < 8; k++) rv1[k] = e1[k * 32 + lane];

        float p0 = 0.f, p1 = 0.f;
#pragma unroll
        for (int k = 0; k < 8; k++) {
            float4 q = sq[k * 32 + lane];
            p0 += rv0[k].x * q.x + rv0[k].y * q.y + rv0[k].z * q.z + rv0[k].w * q.w;
            p1 += rv1[k].x * q.x + rv1[k].y * q.y + rv1[k].z * q.z + rv1[k].w * q.w;
        }
        // two interleaved butterfly reductions (chains overlap)
#pragma unroll
        for (int o = 16; o > 0; o >>= 1) {
            p0 += __shfl_xor_sync(0xffffffffu, p0, o);
            p1 += __shfl_xor_sync(0xffffffffu, p1, o);
        }
        if (!has1) p1 = -INFINITY;            // duplicate row contributes nothing

        float nm = fmaxf(m, fmaxf(p0, p1));
        float sc = __expf(m - nm);
        float w0 = __expf(p0 - nm);
        float w1 = has1 ? __expf(p1 - nm) : 0.f;
#pragma unroll
        for (int k = 0; k < 8; k++) {
            acc[k].x = acc[k].x * sc + w0 * rv0[k].x + w1 * rv1[k].x;
            acc[k].y = acc[k].y * sc + w0 * rv0[k].y + w1 * rv1[k].y;
            acc[k].z = acc[k].z * sc + w0 * rv0[k].z + w1 * rv1[k].z;
            acc[k].w = acc[k].w * sc + w0 * rv0[k].w + w1 * rv1[k].w;
        }
        z = z * sc + w0 + w1;
        m = nm;
    }

    if (lane == 0) sm_[warp] = m;
    __syncthreads();

    float mb = sm_[0];
#pragma unroll
    for (int wv = 1; wv < ATT_WARPS; wv++) mb = fmaxf(mb, sm_[wv]);

    float f = __expf(m - mb);
    if (lane == 0) sz_[warp] = z * f;
#pragma unroll
    for (int k = 0; k < 8; k++) {
        float4 s = make_float4(acc[k].x * f, acc[k].y * f, acc[k].z * f, acc[k].w * f);
        ((float4*)swacc)[warp * (D / 4) + k * 32 + lane] = s;
    }
    __syncthreads();

    // Reduce 8 warp partials; thread tid handles one float4 column
    float* outp = &g_part[blockIdx.x * 1028];
    float4 s = make_float4(0.f, 0.f, 0.f, 0.f);
#pragma unroll
    for (int wv = 0; wv < ATT_WARPS; wv++) {
        float4 v = ((float4*)swacc)[wv * (D / 4) + tid];
        s.x += v.x; s.y += v.y; s.z += v.z; s.w += v.w;
    }
    ((float4*)(outp + 4))[tid] = s;           // offset 4 floats = 16B aligned
    if (tid == 0) {
        float zz = 0.f;
#pragma unroll
        for (int wv = 0; wv < ATT_WARPS; wv++) zz += sz_[wv];
        outp[0] = mb;
        outp[1] = zz;
    }
}

// ---------------------------------------------------------------------------
// K3: combine ATT_BLOCKS partials -> attn vector; writes g_concat[D..2D)
// 32 blocks x 128 threads; 32 columns/block, 4 b-slices per column.
// ---------------------------------------------------------------------------
__global__ void k3_combine() {
    __shared__ float sf[ATT_BLOCKS];
    __shared__ float red[128];
    __shared__ float slice[128];
    int tid = threadIdx.x;

    float lm = -INFINITY;
    for (int b = tid; b < ATT_BLOCKS; b += 128) lm = fmaxf(lm, g_part[b * 1028]);
    red[tid] = lm; __syncthreads();
    for (int s = 64; s > 0; s >>= 1) {
        if (tid < s) red[tid] = fmaxf(red[tid], red[tid + s]);
        __syncthreads();
    }
    float M = red[0]; __syncthreads();

    float lz = 0.f;
    for (int b = tid; b < ATT_BLOCKS; b += 128) {
        float fb = __expf(g_part[b * 1028] - M);
        sf[b] = fb;
        lz += fb * g_part[b * 1028 + 1];
    }
    red[tid] = lz; __syncthreads();
    for (int s = 64; s > 0; s >>= 1) {
        if (tid < s) red[tid] += red[tid + s];
        __syncthreads();
    }
    float invZ = 1.0f / red[0];
    __syncthreads();

    // column sums: 32 columns per block, 4 slices of the b-range per column
    int col = blockIdx.x * 32 + (tid & 31);
    int sl  = tid >> 5;                       // 0..3
    float v = 0.f;
    for (int b = sl; b < ATT_BLOCKS; b += 4)
        v += sf[b] * g_part[b * 1028 + 4 + col];
    slice[tid] = v;
    __syncthreads();
    if (sl == 0) {
        float t = slice[tid] + slice[tid + 32] + slice[tid + 64] + slice[tid + 96];
        g_concat[D + col] = t * invZ;
    }
}

// ---------------------------------------------------------------------------
// K4: logits = W_out @ concat + b_out; one warp per vocab row (412 MB pass).
// EXACT Round-2 form — measured 64.6us @ 6437 GB/s; do not touch.
// ---------------------------------------------------------------------------
__global__ void k4_logits(const float* __restrict__ Wo,
                          const float* __restrict__ bo) {
    __shared__ float4 sc[CDIM / 4];           // 8 KB
    int tid = threadIdx.x, warp = tid >> 5, lane = tid & 31;
    for (int i = tid; i < CDIM / 4; i += blockDim.x)
        sc[i] = ((const float4*)g_concat)[i];
    __syncthreads();

    int v = blockIdx.x * 16 + warp;
    if (v >= VOCAB) return;
    const float4* w4 = (const float4*)(Wo + (size_t)v * CDIM);
    float p = 0.f;
#pragma unroll
    for (int k = 0; k < 16; k++) {
        float4 a = w4[k * 32 + lane];
        float4 q = sc[k * 32 + lane];
        p += a.x * q.x + a.y * q.y + a.z * q.z + a.w * q.w;
    }
    p = warp_reduce_sum(p);
    if (lane == 0) g_logits[v] = p + bo[v];
}

// ---------------------------------------------------------------------------
// K5: one-pass online (max, sumexp) over logits — reads 201KB once from L2
// ---------------------------------------------------------------------------
__global__ void k5_stats() {
    __shared__ float rm[1024], rz[1024];
    int tid = threadIdx.x;
    float m = -INFINITY, z = 0.f;
    for (int i = tid; i < VOCAB; i += 1024) {
        float l  = g_logits[i];
        float nm = fmaxf(m, l);
        z = z * __expf(m - nm) + __expf(l - nm);
        m = nm;
    }
    rm[tid] = m; rz[tid] = z; __syncthreads();
    for (int s = 512; s > 0; s >>= 1) {
        if (tid < s) {
            float m2 = rm[tid + s], z2 = rz[tid + s];
            float nm = fmaxf(rm[tid], m2);
            rz[tid] = rz[tid] * __expf(rm[tid] - nm) + z2 * __expf(m2 - nm);
            rm[tid] = nm;
        }
        __syncthreads();
    }
    if (tid == 0) { g_stats[0] = rm[0]; g_stats[1] = 1.0f / rz[0]; }
}

// ---------------------------------------------------------------------------
// K6: write softmax probabilities
// ---------------------------------------------------------------------------
__global__ void k6_out(float* __restrict__ out) {
    int i = blockIdx.x * 256 + threadIdx.x;
    if (i < VOCAB) out[i] = __expf(g_logits[i] - g_stats[0]) * g_stats[1];
}

// ---------------------------------------------------------------------------
extern "C" void kernel_launch(void* const* d_in, const int* in_sizes, int n_in,
                              void* d_out, int out_size) {
    const float* inp = (const float*)d_in[0];   // [1,1,1024]
    const float* enc = (const float*)d_in[1];   // [32768,1024]
    const float* Wh  = (const float*)d_in[2];   // [1024,1024]
    const float* bh  = (const float*)d_in[3];   // [1024]
    const float* Wo  = (const float*)d_in[4];   // [50257,2048]
    const float* bo  = (const float*)d_in[5];   // [50257]
    float* out = (float*)d_out;                 // [1,50257]

    k1_hidden<<<D / 8, 256>>>(inp, Wh, bh);
    k2_attn<<<ATT_BLOCKS, 256>>>(enc);
    k3_combine<<<D / 32, 128>>>();
    k4_logits<<<(VOCAB + 15) / 16, 512>>>(Wo, bo);
    k5_stats<<<1, 1024>>>();
    k6_out<<<(VOCAB + 255) / 256, 256>>>(out);
}